// round 1
// baseline (speedup 1.0000x reference)
#include <cuda_runtime.h>

#define NN   10000
#define DEG  32
#define FF   512
#define F4   2048

// ---------------- scratch (static device globals; no allocation) ----------
static __device__ float g_Xp[(size_t)NN * F4];   // 82 MB, reused per stage
static __device__ float g_hA[(size_t)NN * FF];
static __device__ float g_hB[(size_t)NN * FF];
static __device__ float g_c [(size_t)NN * FF];
static __device__ float g_hs[(size_t)NN * FF];

__device__ __forceinline__ float sig_(float x) {
    return __fdividef(1.0f, 1.0f + __expf(-x));
}
__device__ __forceinline__ float tanh_(float x) {
    float e = __expf(-2.0f * fabsf(x));
    float t = __fdividef(1.0f - e, 1.0f + e);
    return copysignf(t, x);
}

// ---------------------------------------------------------------------------
// proj: C[n, j] = sum_k A[n,k] * W[j,k] + b1[j] + b2[j]
// A: [NN, 512] row-major, W: [2048, 512] row-major (NT GEMM), C: [NN, 2048]
// grid (157, 32), 256 threads, 64x64 tile, 4x4 per thread
// ---------------------------------------------------------------------------
__global__ void __launch_bounds__(256) proj_kernel(
    const float* __restrict__ A, const float* __restrict__ W,
    const float* __restrict__ b1, const float* __restrict__ b2,
    float* __restrict__ C)
{
    __shared__ float As[16][64];
    __shared__ float Bs[16][64];

    const int bm = blockIdx.x, bn = blockIdx.y;
    const int tid = threadIdx.x;
    const int tx = tid & 15, ty = tid >> 4;
    const int lrow = tid >> 2;          // 0..63
    const int k4   = (tid & 3) << 2;    // 0,4,8,12
    const int grow = bm * 64 + lrow;
    const int wrow = bn * 64 + lrow;

    float acc[4][4] = {};

    for (int kt = 0; kt < FF; kt += 16) {
        float4 av = make_float4(0.f, 0.f, 0.f, 0.f);
        if (grow < NN)
            av = *(const float4*)(A + (size_t)grow * FF + kt + k4);
        float4 bv = *(const float4*)(W + (size_t)wrow * FF + kt + k4);
        As[k4+0][lrow] = av.x; As[k4+1][lrow] = av.y;
        As[k4+2][lrow] = av.z; As[k4+3][lrow] = av.w;
        Bs[k4+0][lrow] = bv.x; Bs[k4+1][lrow] = bv.y;
        Bs[k4+2][lrow] = bv.z; Bs[k4+3][lrow] = bv.w;
        __syncthreads();
        #pragma unroll
        for (int kk = 0; kk < 16; kk++) {
            float4 a  = *(const float4*)&As[kk][ty * 4];
            float4 bb = *(const float4*)&Bs[kk][tx * 4];
            acc[0][0] += a.x*bb.x; acc[0][1] += a.x*bb.y; acc[0][2] += a.x*bb.z; acc[0][3] += a.x*bb.w;
            acc[1][0] += a.y*bb.x; acc[1][1] += a.y*bb.y; acc[1][2] += a.y*bb.z; acc[1][3] += a.y*bb.w;
            acc[2][0] += a.z*bb.x; acc[2][1] += a.z*bb.y; acc[2][2] += a.z*bb.z; acc[2][3] += a.z*bb.w;
            acc[3][0] += a.w*bb.x; acc[3][1] += a.w*bb.y; acc[3][2] += a.w*bb.z; acc[3][3] += a.w*bb.w;
        }
        __syncthreads();
    }

    const int cb = bn * 64 + tx * 4;
    float4 bias;
    bias.x = b1[cb+0] + b2[cb+0];
    bias.y = b1[cb+1] + b2[cb+1];
    bias.z = b1[cb+2] + b2[cb+2];
    bias.w = b1[cb+3] + b2[cb+3];
    #pragma unroll
    for (int i = 0; i < 4; i++) {
        int n = bm * 64 + ty * 4 + i;
        if (n >= NN) break;
        float4 o;
        o.x = acc[i][0] + bias.x; o.y = acc[i][1] + bias.y;
        o.z = acc[i][2] + bias.z; o.w = acc[i][3] + bias.w;
        *(float4*)(C + (size_t)n * F4 + cb) = o;
    }
}

// ---------------------------------------------------------------------------
// first LSTM step (t = 0): h_prev = 0, c_prev = 0  =>  G = Xp[src[:,0]]
// elementwise over NN*FF
// ---------------------------------------------------------------------------
__global__ void __launch_bounds__(256) lstm_first_kernel(
    const float* __restrict__ Xp, const int* __restrict__ src,
    float* __restrict__ c, float* __restrict__ h)
{
    int idx = blockIdx.x * blockDim.x + threadIdx.x;
    if (idx >= NN * FF) return;
    int n  = idx / FF;
    int hc = idx - n * FF;
    int s  = src[n * DEG];
    const float* xr = Xp + (size_t)s * F4 + hc;
    float gi = xr[0];
    float gg = xr[1024];
    float go = xr[1536];
    float cn = sig_(gi) * tanh_(gg);     // sig(f)*c0 term is zero
    c[idx] = cn;
    h[idx] = sig_(go) * tanh_(cn);
}

// ---------------------------------------------------------------------------
// LSTM step t >= 1:
//   G[n, gate*512 + hc] = Xp[src[n,t], gate*512 + hc] + sum_k hprev[n,k] * Whh[gate*512+hc, k]
//   gate update fused in epilogue; c in-place (tile-exclusive), h ping-pong.
// grid (157, 32), 128 threads; block tile: 64 rows x 16 hidden cols x 4 gates
// thread (tx=hc 0..15, ty=rowgrp 0..7): 8 rows x 4 gates = 32 accumulators
// ---------------------------------------------------------------------------
__global__ void __launch_bounds__(128) lstm_step_kernel(
    const float* __restrict__ hprev, const float* __restrict__ Whh,
    const float* __restrict__ Xp,    const int* __restrict__ src,
    int t, float* __restrict__ c, float* __restrict__ hnext)
{
    __shared__ float As[16][64];
    __shared__ float Bs[16][64];   // col index = gate*16 + cc

    const int bm = blockIdx.x;     // row block (157)
    const int bc = blockIdx.y;     // hidden-col block (32)
    const int tid = threadIdx.x;
    const int tx = tid & 15;       // hidden col within tile
    const int ty = tid >> 4;       // 0..7 row group

    float acc0[8] = {}, acc1[8] = {}, acc2[8] = {}, acc3[8] = {};

    for (int kt = 0; kt < FF; kt += 16) {
        #pragma unroll
        for (int l = 0; l < 2; l++) {
            int flat = tid + l * 128;        // 0..255
            int r  = flat >> 2;              // 0..63
            int k4 = (flat & 3) << 2;        // 0,4,8,12
            int gr = bm * 64 + r;
            float4 av = make_float4(0.f, 0.f, 0.f, 0.f);
            if (gr < NN)
                av = *(const float4*)(hprev + (size_t)gr * FF + kt + k4);
            As[k4+0][r] = av.x; As[k4+1][r] = av.y;
            As[k4+2][r] = av.z; As[k4+3][r] = av.w;
            int wr = ((r >> 4) << 9) + bc * 16 + (r & 15);   // gate*512 + bc*16 + cc
            float4 bv = *(const float4*)(Whh + (size_t)wr * FF + kt + k4);
            Bs[k4+0][r] = bv.x; Bs[k4+1][r] = bv.y;
            Bs[k4+2][r] = bv.z; Bs[k4+3][r] = bv.w;
        }
        __syncthreads();
        #pragma unroll
        for (int kk = 0; kk < 16; kk++) {
            float4 a0 = *(const float4*)&As[kk][ty * 8];
            float4 a1 = *(const float4*)&As[kk][ty * 8 + 4];
            float b0 = Bs[kk][tx];
            float b1 = Bs[kk][16 + tx];
            float b2 = Bs[kk][32 + tx];
            float b3 = Bs[kk][48 + tx];
            acc0[0]+=a0.x*b0; acc0[1]+=a0.y*b0; acc0[2]+=a0.z*b0; acc0[3]+=a0.w*b0;
            acc0[4]+=a1.x*b0; acc0[5]+=a1.y*b0; acc0[6]+=a1.z*b0; acc0[7]+=a1.w*b0;
            acc1[0]+=a0.x*b1; acc1[1]+=a0.y*b1; acc1[2]+=a0.z*b1; acc1[3]+=a0.w*b1;
            acc1[4]+=a1.x*b1; acc1[5]+=a1.y*b1; acc1[6]+=a1.z*b1; acc1[7]+=a1.w*b1;
            acc2[0]+=a0.x*b2; acc2[1]+=a0.y*b2; acc2[2]+=a0.z*b2; acc2[3]+=a0.w*b2;
            acc2[4]+=a1.x*b2; acc2[5]+=a1.y*b2; acc2[6]+=a1.z*b2; acc2[7]+=a1.w*b2;
            acc3[0]+=a0.x*b3; acc3[1]+=a0.y*b3; acc3[2]+=a0.z*b3; acc3[3]+=a0.w*b3;
            acc3[4]+=a1.x*b3; acc3[5]+=a1.y*b3; acc3[6]+=a1.z*b3; acc3[7]+=a1.w*b3;
        }
        __syncthreads();
    }

    const int hc = bc * 16 + tx;
    #pragma unroll
    for (int i = 0; i < 8; i++) {
        int n = bm * 64 + ty * 8 + i;
        if (n >= NN) break;
        int s = src[n * DEG + t];
        const float* xr = Xp + (size_t)s * F4 + hc;
        float gi = acc0[i] + xr[0];
        float gf = acc1[i] + xr[512];
        float gg = acc2[i] + xr[1024];
        float go = acc3[i] + xr[1536];
        float co = c[(size_t)n * FF + hc];
        float cn = sig_(gf) * co + sig_(gi) * tanh_(gg);
        c[(size_t)n * FF + hc] = cn;
        hnext[(size_t)n * FF + hc] = sig_(go) * tanh_(cn);
    }
}

// ---------------------------------------------------------------------------
// sage: out[n,j] = sum_k x[n,k]*Ws[k,j] + sum_k hn[n,k]*Wn[k,j] + b[j]
// NN-layout GEMMs, W: [512, 512] row-major. grid (157, 8), 256 threads.
// ---------------------------------------------------------------------------
__global__ void __launch_bounds__(256) sage_kernel(
    const float* __restrict__ x, const float* __restrict__ hn,
    const float* __restrict__ Ws, const float* __restrict__ Wn,
    const float* __restrict__ b, float* __restrict__ out)
{
    __shared__ float As[16][64];
    __shared__ float Bs[16][64];

    const int bm = blockIdx.x, bn = blockIdx.y;
    const int tid = threadIdx.x;
    const int tx = tid & 15, ty = tid >> 4;
    const int lrow = tid >> 2;
    const int k4   = (tid & 3) << 2;
    const int grow = bm * 64 + lrow;
    const int kr = tid >> 4;            // 0..15 (B tile row)
    const int jc = (tid & 15) << 2;     // 0..60 (B tile col)

    float acc[4][4] = {};

    #pragma unroll 1
    for (int p = 0; p < 2; p++) {
        const float* A = p ? hn : x;
        const float* W = p ? Wn : Ws;
        for (int kt = 0; kt < FF; kt += 16) {
            float4 av = make_float4(0.f, 0.f, 0.f, 0.f);
            if (grow < NN)
                av = *(const float4*)(A + (size_t)grow * FF + kt + k4);
            As[k4+0][lrow] = av.x; As[k4+1][lrow] = av.y;
            As[k4+2][lrow] = av.z; As[k4+3][lrow] = av.w;
            float4 bv = *(const float4*)(W + (size_t)(kt + kr) * FF + bn * 64 + jc);
            *(float4*)&Bs[kr][jc] = bv;
            __syncthreads();
            #pragma unroll
            for (int kk = 0; kk < 16; kk++) {
                float4 a  = *(const float4*)&As[kk][ty * 4];
                float4 bb = *(const float4*)&Bs[kk][tx * 4];
                acc[0][0] += a.x*bb.x; acc[0][1] += a.x*bb.y; acc[0][2] += a.x*bb.z; acc[0][3] += a.x*bb.w;
                acc[1][0] += a.y*bb.x; acc[1][1] += a.y*bb.y; acc[1][2] += a.y*bb.z; acc[1][3] += a.y*bb.w;
                acc[2][0] += a.z*bb.x; acc[2][1] += a.z*bb.y; acc[2][2] += a.z*bb.z; acc[2][3] += a.z*bb.w;
                acc[3][0] += a.w*bb.x; acc[3][1] += a.w*bb.y; acc[3][2] += a.w*bb.z; acc[3][3] += a.w*bb.w;
            }
            __syncthreads();
        }
    }

    const int cb = bn * 64 + tx * 4;
    float4 bias = *(const float4*)(b + cb);
    #pragma unroll
    for (int i = 0; i < 4; i++) {
        int n = bm * 64 + ty * 4 + i;
        if (n >= NN) break;
        float4 o;
        o.x = acc[i][0] + bias.x; o.y = acc[i][1] + bias.y;
        o.z = acc[i][2] + bias.z; o.w = acc[i][3] + bias.w;
        *(float4*)(out + (size_t)n * FF + cb) = o;
    }
}

// ---------------------------------------------------------------------------
extern "C" void kernel_launch(void* const* d_in, const int* in_sizes, int n_in,
                              void* d_out, int out_size)
{
    const float* x      = (const float*)d_in[0];
    const int*   src    = (const int*)  d_in[1];
    const float* Wih1   = (const float*)d_in[2];
    const float* Whh1   = (const float*)d_in[3];
    const float* bih1   = (const float*)d_in[4];
    const float* bhh1   = (const float*)d_in[5];
    const float* Wself  = (const float*)d_in[6];
    const float* Wneigh = (const float*)d_in[7];
    const float* b      = (const float*)d_in[8];
    const float* Wih2   = (const float*)d_in[9];
    const float* Whh2   = (const float*)d_in[10];
    const float* bih2   = (const float*)d_in[11];
    const float* bhh2   = (const float*)d_in[12];
    float* out = (float*)d_out;

    float *Xp, *hA, *hB, *c, *hs;
    cudaGetSymbolAddress((void**)&Xp, g_Xp);
    cudaGetSymbolAddress((void**)&hA, g_hA);
    cudaGetSymbolAddress((void**)&hB, g_hB);
    cudaGetSymbolAddress((void**)&c,  g_c);
    cudaGetSymbolAddress((void**)&hs, g_hs);

    const int RB = (NN + 63) / 64;           // 157
    dim3 gProj(RB, F4 / 64);                  // (157, 32)
    dim3 gStep(RB, FF / 16);                  // (157, 32)
    dim3 gSage(RB, FF / 64);                  // (157, 8)
    int  gFirst = (NN * FF + 255) / 256;

    // ---- Stage 1: SAGEConv internal LSTM over x-mailbox ----
    proj_kernel<<<gProj, 256>>>(x, Wih1, bih1, bhh1, Xp);
    lstm_first_kernel<<<gFirst, 256>>>(Xp, src, c, hA);
    for (int t = 1; t < DEG; t++) {
        float* hp = (t & 1) ? hA : hB;
        float* hn = (t & 1) ? hB : hA;
        lstm_step_kernel<<<gStep, 128>>>(hp, Whh1, Xp, src, t, c, hn);
    }
    // t=31 (odd) wrote hB -> h_neigh = hB

    // ---- SAGE linear ----
    sage_kernel<<<gSage, 256>>>(x, hB, Wself, Wneigh, b, hs);

    // ---- Stage 2: outer LSTM over h-mailbox ----
    proj_kernel<<<gProj, 256>>>(hs, Wih2, bih2, bhh2, Xp);
    lstm_first_kernel<<<gFirst, 256>>>(Xp, src, c, hA);
    for (int t = 1; t < DEG; t++) {
        float* hp = (t & 1) ? hA : hB;
        float* hn = (t == DEG - 1) ? out : ((t & 1) ? hB : hA);
        lstm_step_kernel<<<gStep, 128>>>(hp, Whh2, Xp, src, t, c, hn);
    }
}

// round 3
// speedup vs baseline: 1.7558x; 1.7558x over previous
#include <cuda_runtime.h>
#include <cuda_fp16.h>
#include <cstdint>

#define NN   10000
#define DEG  32
#define FF   512

// ---------------- scratch (static device globals; no allocation) ----------
static __device__ float  g_Xp   [(size_t)NN * 2048];   // 82 MB gate pre-activations (interleaved col = 4*hc+gate)
static __device__ __half g_sageA[(size_t)NN * 2048];   // [x_hi | x_lo64 | hn_hi | hn_lo64]
static __device__ __half g_hA   [(size_t)NN * 1024];   // h split ping  [hi | lo64]
static __device__ __half g_hB   [(size_t)NN * 1024];   // h split pong
static __device__ __half g_Wb   [(size_t)2048 * 1024]; // recurrent/proj W split (interleaved rows)
static __device__ __half g_WbS  [(size_t)512 * 2048];  // sage W split
static __device__ float  g_bsum [2048];
static __device__ float  g_c    [(size_t)NN * FF];

__device__ __forceinline__ float sig_(float x) {
    return __fdividef(1.0f, 1.0f + __expf(-x));
}
__device__ __forceinline__ float tanh_(float x) {
    float e = __expf(-2.0f * fabsf(x));
    float t = __fdividef(1.0f - e, 1.0f + e);
    return copysignf(t, x);
}

__device__ __forceinline__ uint32_t smem_u32(const void* p) {
    uint32_t a;
    asm("{ .reg .u64 t; cvta.to.shared.u64 t, %1; cvt.u32.u64 %0, t; }" : "=r"(a) : "l"(p));
    return a;
}
__device__ __forceinline__ void cpa16(uint32_t saddr, const void* g, int ss) {
    asm volatile("cp.async.cg.shared.global [%0], [%1], 16, %2;"
                 :: "r"(saddr), "l"(g), "r"(ss) : "memory");
}
__device__ __forceinline__ void ldsm4(uint32_t* r, uint32_t addr) {
    asm volatile("ldmatrix.sync.aligned.m8n8.x4.shared.b16 {%0,%1,%2,%3}, [%4];"
                 : "=r"(r[0]), "=r"(r[1]), "=r"(r[2]), "=r"(r[3]) : "r"(addr));
}
__device__ __forceinline__ void mma16816(float* d, const uint32_t* a, const uint32_t* b) {
    asm volatile("mma.sync.aligned.m16n8k16.row.col.f32.f16.f16.f32 "
                 "{%0,%1,%2,%3}, {%4,%5,%6,%7}, {%8,%9}, {%0,%1,%2,%3};"
                 : "+f"(d[0]), "+f"(d[1]), "+f"(d[2]), "+f"(d[3])
                 : "r"(a[0]), "r"(a[1]), "r"(a[2]), "r"(a[3]), "r"(b[0]), "r"(b[1]));
}

// tile geometry: block 128x128, 512 threads (16 warps, 4m x 4n), warp 32x32
// smem tile: 128 rows x 32 halfs, padded stride 40 halfs (80B, ldmatrix conflict-free)
#define PAD     40
#define TILE_B  10240              // 128*40*2
#define BUF_B   40960              // 4 tiles (Ahi, Alo, Bhi, Blo)
#define SMEMB   81920              // double buffered

// ---------------------------------------------------------------------------
// GEMM: C[m, n] = A2[m,:] . B2[n,:]  with fp16 split dedup
//   per segment s: A hi at [s*1024+k], lo*64 at [s*1024+512+k]; B likewise.
//   C = P + S/64, P = hi.Whi, S = lo64.Whi + hi.Wlo64
// mode 0: proj   -> XpOut[r*2048 + c] = C + bias[c]
// mode 1: LSTM   -> gate epilogue (Xp gather, c update, h split/fp32 out)
// mode 2: sage   -> split(C + bias[c]) -> hout (stride hstride, offset hoff)
// ---------------------------------------------------------------------------
__global__ void __launch_bounds__(512) gemm_f16_kernel(
    const __half* __restrict__ A, int lda,
    const __half* __restrict__ B, int nseg, int mode,
    const float* __restrict__ bias, float* __restrict__ XpOut,
    const float* __restrict__ XpIn, const int* __restrict__ src, int t,
    float* __restrict__ cbuf,
    __half* __restrict__ hout, int hstride, int hoff,
    float* __restrict__ h32out)
{
    extern __shared__ __align__(16) char smem[];
    const uint32_t sbase = smem_u32(smem);
    const int tid  = threadIdx.x;
    const int warp = tid >> 5, lane = tid & 31;
    const int wm = warp & 3, wn = warp >> 2;
    const int m0 = blockIdx.x * 128, n0 = blockIdx.y * 128;
    const int ldb = nseg << 10;
    const int nch = nseg << 4;

    float accP[2][4][4], accS[2][4][4];
    #pragma unroll
    for (int i = 0; i < 2; i++)
        #pragma unroll
        for (int j = 0; j < 4; j++)
            #pragma unroll
            for (int r = 0; r < 4; r++) { accP[i][j][r] = 0.f; accS[i][j][r] = 0.f; }

    // per-thread load mapping: 4 x cp.async(16B) per chunk
    const int lrow = tid >> 2, lseg = tid & 3;
    const int arow = m0 + lrow;
    const int asz  = (arow < NN) ? 16 : 0;
    const size_t aG = (size_t)((arow < NN) ? arow : 0) * lda + lseg * 8;
    const size_t bG = (size_t)(n0 + lrow) * ldb + lseg * 8;
    const uint32_t sOff = (uint32_t)(lrow * PAD + lseg * 8) * 2;

    // ldmatrix per-thread offsets
    const uint32_t aB = (uint32_t)((wm * 32 + (lane & 15)) * PAD + ((lane >> 4) & 1) * 8) * 2;
    const uint32_t bB = (uint32_t)((wn * 32 + (lane & 7) + ((lane >> 4) << 3)) * PAD
                                   + ((lane >> 3) & 1) * 8) * 2;

    auto issue = [&](int ch, int buf) {
        const int seg = ch >> 4;
        const int kk  = (ch & 15) << 5;
        const __half* ga = A + aG + seg * 1024 + kk;
        const __half* gb = B + bG + seg * 1024 + kk;
        const uint32_t s0 = sbase + buf * BUF_B;
        cpa16(s0 +           sOff, ga,        asz);
        cpa16(s0 + TILE_B  + sOff, ga + 512,  asz);
        cpa16(s0 + 2*TILE_B + sOff, gb,       16);
        cpa16(s0 + 3*TILE_B + sOff, gb + 512, 16);
        asm volatile("cp.async.commit_group;" ::: "memory");
    };

    issue(0, 0);
    #pragma unroll 1
    for (int ch = 0; ch < nch; ch++) {
        asm volatile("cp.async.wait_group 0;" ::: "memory");
        __syncthreads();
        if (ch + 1 < nch) issue(ch + 1, (ch + 1) & 1);
        const uint32_t s0 = sbase + (ch & 1) * BUF_B;
        #pragma unroll
        for (int st = 0; st < 2; st++) {
            uint32_t aH[2][4], aL[2][4], bH[2][4], bL[2][4];
            ldsm4(aH[0], s0 + aB + st * 32);
            ldsm4(aH[1], s0 + aB + 1280 + st * 32);
            ldsm4(aL[0], s0 + TILE_B + aB + st * 32);
            ldsm4(aL[1], s0 + TILE_B + aB + 1280 + st * 32);
            ldsm4(bH[0], s0 + 2*TILE_B + bB + st * 32);
            ldsm4(bH[1], s0 + 2*TILE_B + bB + 1280 + st * 32);
            ldsm4(bL[0], s0 + 3*TILE_B + bB + st * 32);
            ldsm4(bL[1], s0 + 3*TILE_B + bB + 1280 + st * 32);
            #pragma unroll
            for (int i = 0; i < 2; i++)
                #pragma unroll
                for (int j = 0; j < 4; j++) {
                    const uint32_t* bh = &bH[j >> 1][(j & 1) * 2];
                    const uint32_t* bl = &bL[j >> 1][(j & 1) * 2];
                    mma16816(accP[i][j], aH[i], bh);
                    mma16816(accS[i][j], aL[i], bh);
                    mma16816(accS[i][j], aH[i], bl);
                }
        }
    }

    const float inv64 = 0.015625f;

    if (mode != 1) {
        #pragma unroll
        for (int i = 0; i < 2; i++)
            #pragma unroll
            for (int j = 0; j < 4; j++) {
                const int c0 = n0 + wn * 32 + j * 8 + (lane & 3) * 2;
                const int r1 = m0 + wm * 32 + i * 16 + (lane >> 2);
                const float2 bs = *(const float2*)(bias + c0);
                float v0 = accP[i][j][0] + accS[i][j][0] * inv64 + bs.x;
                float v1 = accP[i][j][1] + accS[i][j][1] * inv64 + bs.y;
                float v2 = accP[i][j][2] + accS[i][j][2] * inv64 + bs.x;
                float v3 = accP[i][j][3] + accS[i][j][3] * inv64 + bs.y;
                if (mode == 0) {
                    if (r1 < NN)     *(float2*)(XpOut + (size_t)r1 * 2048 + c0) = make_float2(v0, v1);
                    if (r1 + 8 < NN) *(float2*)(XpOut + (size_t)(r1 + 8) * 2048 + c0) = make_float2(v2, v3);
                } else {  // mode 2: split write
                    if (r1 < NN) {
                        __half h0 = __float2half_rn(v0), h1 = __float2half_rn(v1);
                        __half l0 = __float2half_rn((v0 - __half2float(h0)) * 64.f);
                        __half l1 = __float2half_rn((v1 - __half2float(h1)) * 64.f);
                        size_t o = (size_t)r1 * hstride + hoff + c0;
                        *(__half2*)(hout + o)       = __halves2half2(h0, h1);
                        *(__half2*)(hout + o + 512) = __halves2half2(l0, l1);
                    }
                    if (r1 + 8 < NN) {
                        __half h0 = __float2half_rn(v2), h1 = __float2half_rn(v3);
                        __half l0 = __float2half_rn((v2 - __half2float(h0)) * 64.f);
                        __half l1 = __float2half_rn((v3 - __half2float(h1)) * 64.f);
                        size_t o = (size_t)(r1 + 8) * hstride + hoff + c0;
                        *(__half2*)(hout + o)       = __halves2half2(h0, h1);
                        *(__half2*)(hout + o + 512) = __halves2half2(l0, l1);
                    }
                }
            }
    } else {
        #pragma unroll
        for (int i = 0; i < 2; i++)
            #pragma unroll
            for (int j = 0; j < 4; j++) {
                float v0 = accP[i][j][0] + accS[i][j][0] * inv64;
                float v1 = accP[i][j][1] + accS[i][j][1] * inv64;
                float v2 = accP[i][j][2] + accS[i][j][2] * inv64;
                float v3 = accP[i][j][3] + accS[i][j][3] * inv64;
                const float p0 = __shfl_xor_sync(0xffffffffu, v0, 1);
                const float p1 = __shfl_xor_sync(0xffffffffu, v1, 1);
                const float p2 = __shfl_xor_sync(0xffffffffu, v2, 1);
                const float p3 = __shfl_xor_sync(0xffffffffu, v3, 1);
                const int q = lane & 1;
                const int rowU = m0 + wm * 32 + i * 16 + (lane >> 2) + (q << 3);
                const int hc = ((n0 + wn * 32 + j * 8) >> 2) + ((lane & 3) >> 1);
                if (rowU < NN) {
                    float gi, gf, gg, go;
                    if (!q) { gi = v0; gf = v1; gg = p0; go = p1; }
                    else    { gi = p2; gf = p3; gg = v2; go = v3; }
                    const int s = src[rowU * DEG + t];
                    const float4 xv = *(const float4*)(XpIn + (size_t)s * 2048 + 4 * hc);
                    gi += xv.x; gf += xv.y; gg += xv.z; go += xv.w;
                    const size_t ci = (size_t)rowU * FF + hc;
                    const float cn = sig_(gf) * cbuf[ci] + sig_(gi) * tanh_(gg);
                    cbuf[ci] = cn;
                    const float hv = sig_(go) * tanh_(cn);
                    if (h32out) h32out[ci] = hv;
                    if (hout) {
                        const __half hh = __float2half_rn(hv);
                        hout[(size_t)rowU * hstride + hoff + hc] = hh;
                        hout[(size_t)rowU * hstride + hoff + 512 + hc] =
                            __float2half_rn((hv - __half2float(hh)) * 64.f);
                    }
                }
            }
    }
}

// ---------------------------------------------------------------------------
// conv_w: W fp32 [2048,512] (rows gate*512+hc) -> split [2048,1024] interleaved
// row jp = 4*hc+gate; hi at [jp,k], lo*64 at [jp,512+k]; bsum[jp] = b1+b2.
// ---------------------------------------------------------------------------
__global__ void __launch_bounds__(256) conv_w_kernel(
    const float* __restrict__ W, const float* __restrict__ b1, const float* __restrict__ b2,
    __half* __restrict__ W2, float* __restrict__ bsum)
{
    const int idx = blockIdx.x * 256 + threadIdx.x;
    if (idx >= 2048 * 512) return;
    const int jp = idx >> 9, k = idx & 511;
    const int orig = (jp & 3) * 512 + (jp >> 2);
    const float w = W[(size_t)orig * 512 + k];
    const __half hi = __float2half_rn(w);
    W2[(size_t)jp * 1024 + k] = hi;
    W2[(size_t)jp * 1024 + 512 + k] = __float2half_rn((w - __half2float(hi)) * 64.f);
    if (k == 0 && bsum) bsum[jp] = b1[orig] + b2[orig];
}

// conv_w_sage: WbS[512,2048] = [Wself^T hi | Wself^T lo64 | Wneigh^T hi | Wneigh^T lo64]
__global__ void __launch_bounds__(256) conv_w_sage_kernel(
    const float* __restrict__ Ws, const float* __restrict__ Wn,
    __half* __restrict__ W2)
{
    const int idx = blockIdx.x * 256 + threadIdx.x;
    if (idx >= 512 * 512) return;
    const int j = idx >> 9, k = idx & 511;
    const float ws = Ws[(size_t)k * 512 + j];
    const float wn = Wn[(size_t)k * 512 + j];
    const __half hs = __float2half_rn(ws), hn = __float2half_rn(wn);
    const size_t base = (size_t)j * 2048;
    W2[base + k]        = hs;
    W2[base + 512 + k]  = __float2half_rn((ws - __half2float(hs)) * 64.f);
    W2[base + 1024 + k] = hn;
    W2[base + 1536 + k] = __float2half_rn((wn - __half2float(hn)) * 64.f);
}

// conv_a: x fp32 [NN,512] -> split into sageA first half (stride 2048)
__global__ void __launch_bounds__(256) conv_a_kernel(
    const float* __restrict__ X, __half* __restrict__ A2)
{
    const int idx = blockIdx.x * 256 + threadIdx.x;
    if (idx >= NN * 512) return;
    const int n = idx >> 9, k = idx & 511;
    const float v = X[idx];
    const __half hi = __float2half_rn(v);
    A2[(size_t)n * 2048 + k] = hi;
    A2[(size_t)n * 2048 + 512 + k] = __float2half_rn((v - __half2float(hi)) * 64.f);
}

// first LSTM step (t=0): gates = Xp[src[:,0]] (h0=c0=0); write c + h split
__global__ void __launch_bounds__(256) lstm_first_kernel(
    const float* __restrict__ Xp, const int* __restrict__ src,
    float* __restrict__ c, __half* __restrict__ hout)
{
    const int idx = blockIdx.x * 256 + threadIdx.x;
    if (idx >= NN * 512) return;
    const int n = idx >> 9, hc = idx & 511;
    const int s = src[n * DEG];
    const float4 xv = *(const float4*)(Xp + (size_t)s * 2048 + 4 * hc);
    const float cn = sig_(xv.x) * tanh_(xv.z);
    c[idx] = cn;
    const float hv = sig_(xv.w) * tanh_(cn);
    const __half hh = __float2half_rn(hv);
    hout[(size_t)n * 1024 + hc] = hh;
    hout[(size_t)n * 1024 + 512 + hc] = __float2half_rn((hv - __half2float(hh)) * 64.f);
}

// ---------------------------------------------------------------------------
extern "C" void kernel_launch(void* const* d_in, const int* in_sizes, int n_in,
                              void* d_out, int out_size)
{
    const float* x      = (const float*)d_in[0];
    const int*   src    = (const int*)  d_in[1];
    const float* Wih1   = (const float*)d_in[2];
    const float* Whh1   = (const float*)d_in[3];
    const float* bih1   = (const float*)d_in[4];
    const float* bhh1   = (const float*)d_in[5];
    const float* Wself  = (const float*)d_in[6];
    const float* Wneigh = (const float*)d_in[7];
    const float* b      = (const float*)d_in[8];
    const float* Wih2   = (const float*)d_in[9];
    const float* Whh2   = (const float*)d_in[10];
    const float* bih2   = (const float*)d_in[11];
    const float* bhh2   = (const float*)d_in[12];
    float* out = (float*)d_out;

    float *Xp, *bsum, *c;
    __half *sageA, *hA, *hB, *Wb, *WbS;
    cudaGetSymbolAddress((void**)&Xp,    g_Xp);
    cudaGetSymbolAddress((void**)&sageA, g_sageA);
    cudaGetSymbolAddress((void**)&hA,    g_hA);
    cudaGetSymbolAddress((void**)&hB,    g_hB);
    cudaGetSymbolAddress((void**)&Wb,    g_Wb);
    cudaGetSymbolAddress((void**)&WbS,   g_WbS);
    cudaGetSymbolAddress((void**)&bsum,  g_bsum);
    cudaGetSymbolAddress((void**)&c,     g_c);

    cudaFuncSetAttribute(gemm_f16_kernel,
                         cudaFuncAttributeMaxDynamicSharedMemorySize, SMEMB);

    const dim3 gMain((NN + 127) / 128, 16);   // 2048 output cols
    const dim3 gSage((NN + 127) / 128, 4);    // 512 output cols
    const int  gElem  = (NN * 512) / 256;
    const int  gConvW = (2048 * 512) / 256;
    const int  gConvS = (512 * 512) / 256;

    // ================= Stage 1 =================
    conv_w_kernel<<<gConvW, 256>>>(Wih1, bih1, bhh1, Wb, bsum);
    conv_a_kernel<<<gElem, 256>>>(x, sageA);
    gemm_f16_kernel<<<gMain, 512, SMEMB>>>(sageA, 2048, Wb, 1, 0,
        bsum, Xp, nullptr, nullptr, 0, nullptr, nullptr, 0, 0, nullptr);
    conv_w_kernel<<<gConvW, 256>>>(Whh1, nullptr, nullptr, Wb, nullptr);
    lstm_first_kernel<<<gElem, 256>>>(Xp, src, c, hB);          // h(0) -> hB
    for (int t = 1; t <= 30; t++) {
        __half* hin  = (t & 1) ? hB : hA;
        __half* hout = (t & 1) ? hA : hB;
        gemm_f16_kernel<<<gMain, 512, SMEMB>>>(hin, 1024, Wb, 1, 1,
            nullptr, nullptr, Xp, src, t, c, hout, 1024, 0, nullptr);
    }
    // t=31: h_neigh split -> sageA second half
    gemm_f16_kernel<<<gMain, 512, SMEMB>>>(hB, 1024, Wb, 1, 1,
        nullptr, nullptr, Xp, src, 31, c, sageA, 2048, 1024, nullptr);

    // ---- SAGE linear (split output -> hA) ----
    conv_w_sage_kernel<<<gConvS, 256>>>(Wself, Wneigh, WbS);
    gemm_f16_kernel<<<gSage, 512, SMEMB>>>(sageA, 2048, WbS, 2, 2,
        b, nullptr, nullptr, nullptr, 0, nullptr, hA, 1024, 0, nullptr);

    // ================= Stage 2 =================
    conv_w_kernel<<<gConvW, 256>>>(Wih2, bih2, bhh2, Wb, bsum);
    gemm_f16_kernel<<<gMain, 512, SMEMB>>>(hA, 1024, Wb, 1, 0,
        bsum, Xp, nullptr, nullptr, 0, nullptr, nullptr, 0, 0, nullptr);
    conv_w_kernel<<<gConvW, 256>>>(Whh2, nullptr, nullptr, Wb, nullptr);
    lstm_first_kernel<<<gElem, 256>>>(Xp, src, c, hB);
    for (int t = 1; t <= 30; t++) {
        __half* hin  = (t & 1) ? hB : hA;
        __half* hout = (t & 1) ? hA : hB;
        gemm_f16_kernel<<<gMain, 512, SMEMB>>>(hin, 1024, Wb, 1, 1,
            nullptr, nullptr, Xp, src, t, c, hout, 1024, 0, nullptr);
    }
    gemm_f16_kernel<<<gMain, 512, SMEMB>>>(hB, 1024, Wb, 1, 1,
        nullptr, nullptr, Xp, src, 31, c, nullptr, 0, 0, out);
}

// round 4
// speedup vs baseline: 1.7931x; 1.0213x over previous
#include <cuda_runtime.h>
#include <cuda_fp16.h>
#include <cstdint>

#define NN   10000
#define DEG  32
#define FF   512

// ---------------- scratch (static device globals; no allocation) ----------
static __device__ float  g_Xp   [(size_t)NN * 2048];   // gate pre-activations (col = 4*hc+gate)
static __device__ __half g_sageA[(size_t)NN * 2048];   // [x_hi | x_lo64 | hn_hi | hn_lo64]
static __device__ __half g_hA   [(size_t)NN * 1024];   // h split ping  [hi | lo64]
static __device__ __half g_hB   [(size_t)NN * 1024];   // h split pong
static __device__ __half g_Wb   [(size_t)2048 * 1024]; // recurrent/proj W split (interleaved rows)
static __device__ __half g_WbS  [(size_t)512 * 2048];  // sage W split
static __device__ float  g_bsum [2048];
static __device__ float  g_c    [(size_t)NN * FF];

__device__ __forceinline__ float sig_(float x) {
    return __fdividef(1.0f, 1.0f + __expf(-x));
}
__device__ __forceinline__ float tanh_(float x) {
    float e = __expf(-2.0f * fabsf(x));
    float t = __fdividef(1.0f - e, 1.0f + e);
    return copysignf(t, x);
}

__device__ __forceinline__ uint32_t smem_u32(const void* p) {
    uint32_t a;
    asm("{ .reg .u64 t; cvta.to.shared.u64 t, %1; cvt.u32.u64 %0, t; }" : "=r"(a) : "l"(p));
    return a;
}
__device__ __forceinline__ void cpa16(uint32_t saddr, const void* g, int ss) {
    asm volatile("cp.async.cg.shared.global [%0], [%1], 16, %2;"
                 :: "r"(saddr), "l"(g), "r"(ss) : "memory");
}
__device__ __forceinline__ void ldsm4(uint32_t* r, uint32_t addr) {
    asm volatile("ldmatrix.sync.aligned.m8n8.x4.shared.b16 {%0,%1,%2,%3}, [%4];"
                 : "=r"(r[0]), "=r"(r[1]), "=r"(r[2]), "=r"(r[3]) : "r"(addr));
}
// fp32-accumulator HMMA (primary term)
__device__ __forceinline__ void mma16816(float* d, const uint32_t* a, const uint32_t* b) {
    asm volatile("mma.sync.aligned.m16n8k16.row.col.f32.f16.f16.f32 "
                 "{%0,%1,%2,%3}, {%4,%5,%6,%7}, {%8,%9}, {%0,%1,%2,%3};"
                 : "+f"(d[0]), "+f"(d[1]), "+f"(d[2]), "+f"(d[3])
                 : "r"(a[0]), "r"(a[1]), "r"(a[2]), "r"(a[3]), "r"(b[0]), "r"(b[1]));
}
// fp16-accumulator HMMA (2x rate; correction terms only)
__device__ __forceinline__ void mma16816h(uint32_t* d, const uint32_t* a, const uint32_t* b) {
    asm volatile("mma.sync.aligned.m16n8k16.row.col.f16.f16.f16.f16 "
                 "{%0,%1}, {%2,%3,%4,%5}, {%6,%7}, {%0,%1};"
                 : "+r"(d[0]), "+r"(d[1])
                 : "r"(a[0]), "r"(a[1]), "r"(a[2]), "r"(a[3]), "r"(b[0]), "r"(b[1]));
}

// tile geometry: block 128x128, 512 threads (16 warps, 4m x 4n), warp 32x32
// smem tile: 128 rows x 32 halfs, padded stride 40 halfs (conflict-free ldmatrix)
#define PAD     40
#define TILE_B  10240              // 128*40*2
#define BUF_B   40960              // 4 tiles (Ahi, Alo, Bhi, Blo)
#define NSTAGE  3
#define SMEMB   (NSTAGE * BUF_B)   // 122,880 bytes

// ---------------------------------------------------------------------------
// GEMM: C[m, n] = A2[m,:] . B2[n,:]  with fp16 split dedup
//   per segment s: A hi at [s*1024+k], lo*64 at [s*1024+512+k]; B likewise.
//   C = P + S/64, P = hi.Whi (f32 acc), S = lo64.Whi + hi.Wlo64 (f16 acc)
// mode 0: proj   -> XpOut[r*2048 + c] = C + bias[c]
// mode 1: LSTM   -> gate epilogue (Xp gather, c update, h split/fp32 out)
// mode 2: sage   -> split(C + bias[c]) -> hout (stride hstride, offset hoff)
// ---------------------------------------------------------------------------
__global__ void __launch_bounds__(512) gemm_f16_kernel(
    const __half* __restrict__ A, int lda,
    const __half* __restrict__ B, int nseg, int mode,
    const float* __restrict__ bias, float* __restrict__ XpOut,
    const float* __restrict__ XpIn, const int* __restrict__ src, int t,
    float* __restrict__ cbuf,
    __half* __restrict__ hout, int hstride, int hoff,
    float* __restrict__ h32out)
{
    extern __shared__ __align__(16) char smem[];
    const uint32_t sbase = smem_u32(smem);
    const int tid  = threadIdx.x;
    const int warp = tid >> 5, lane = tid & 31;
    const int wm = warp & 3, wn = warp >> 2;
    const int m0 = blockIdx.x * 128, n0 = blockIdx.y * 128;
    const int ldb = nseg << 10;
    const int nch = nseg << 4;

    float    accP[2][4][4];
    uint32_t accS[2][4][2];
    #pragma unroll
    for (int i = 0; i < 2; i++)
        #pragma unroll
        for (int j = 0; j < 4; j++) {
            #pragma unroll
            for (int r = 0; r < 4; r++) accP[i][j][r] = 0.f;
            accS[i][j][0] = 0u; accS[i][j][1] = 0u;
        }

    // per-thread load mapping: 4 x cp.async(16B) per chunk
    const int lrow = tid >> 2, lseg = tid & 3;
    const int arow = m0 + lrow;
    const int asz  = (arow < NN) ? 16 : 0;
    const size_t aG = (size_t)((arow < NN) ? arow : 0) * lda + lseg * 8;
    const size_t bG = (size_t)(n0 + lrow) * ldb + lseg * 8;
    const uint32_t sOff = (uint32_t)(lrow * PAD + lseg * 8) * 2;

    // ldmatrix per-thread offsets
    const uint32_t aB = (uint32_t)((wm * 32 + (lane & 15)) * PAD + ((lane >> 4) & 1) * 8) * 2;
    const uint32_t bB = (uint32_t)((wn * 32 + (lane & 7) + ((lane >> 4) << 3)) * PAD
                                   + ((lane >> 3) & 1) * 8) * 2;

    auto issue = [&](int ch, int buf) {
        const int seg = ch >> 4;
        const int kk  = (ch & 15) << 5;
        const __half* ga = A + aG + seg * 1024 + kk;
        const __half* gb = B + bG + seg * 1024 + kk;
        const uint32_t s0 = sbase + buf * BUF_B;
        cpa16(s0 +            sOff, ga,        asz);
        cpa16(s0 + TILE_B   + sOff, ga + 512,  asz);
        cpa16(s0 + 2*TILE_B + sOff, gb,        16);
        cpa16(s0 + 3*TILE_B + sOff, gb + 512,  16);
        asm volatile("cp.async.commit_group;" ::: "memory");
    };

    issue(0, 0);
    issue(1, 1);
    int buf = 0;
    #pragma unroll 1
    for (int ch = 0; ch < nch; ch++) {
        if (ch + 1 < nch)
            asm volatile("cp.async.wait_group 1;" ::: "memory");
        else
            asm volatile("cp.async.wait_group 0;" ::: "memory");
        __syncthreads();
        if (ch + 2 < nch) {
            int nb = buf + 2; if (nb >= NSTAGE) nb -= NSTAGE;
            issue(ch + 2, nb);
        }
        const uint32_t s0 = sbase + buf * BUF_B;
        #pragma unroll
        for (int st = 0; st < 2; st++) {
            uint32_t aH[2][4], aL[2][4], bH[2][4], bL[2][4];
            ldsm4(aH[0], s0 + aB + st * 32);
            ldsm4(aH[1], s0 + aB + 1280 + st * 32);
            ldsm4(aL[0], s0 + TILE_B + aB + st * 32);
            ldsm4(aL[1], s0 + TILE_B + aB + 1280 + st * 32);
            ldsm4(bH[0], s0 + 2*TILE_B + bB + st * 32);
            ldsm4(bH[1], s0 + 2*TILE_B + bB + 1280 + st * 32);
            ldsm4(bL[0], s0 + 3*TILE_B + bB + st * 32);
            ldsm4(bL[1], s0 + 3*TILE_B + bB + 1280 + st * 32);
            #pragma unroll
            for (int i = 0; i < 2; i++)
                #pragma unroll
                for (int j = 0; j < 4; j++) {
                    const uint32_t* bh = &bH[j >> 1][(j & 1) * 2];
                    const uint32_t* bl = &bL[j >> 1][(j & 1) * 2];
                    mma16816(accP[i][j], aH[i], bh);
                    mma16816h(accS[i][j], aL[i], bh);
                    mma16816h(accS[i][j], aH[i], bl);
                }
        }
        buf++; if (buf >= NSTAGE) buf -= NSTAGE;
    }

    const float inv64 = 0.015625f;

    if (mode != 1) {
        #pragma unroll
        for (int i = 0; i < 2; i++)
            #pragma unroll
            for (int j = 0; j < 4; j++) {
                const int c0 = n0 + wn * 32 + j * 8 + (lane & 3) * 2;
                const int r1 = m0 + wm * 32 + i * 16 + (lane >> 2);
                const float2 bs = *(const float2*)(bias + c0);
                const __half2 sA = *(const __half2*)&accS[i][j][0];
                const __half2 sB = *(const __half2*)&accS[i][j][1];
                float v0 = accP[i][j][0] + __half2float(__low2half(sA))  * inv64 + bs.x;
                float v1 = accP[i][j][1] + __half2float(__high2half(sA)) * inv64 + bs.y;
                float v2 = accP[i][j][2] + __half2float(__low2half(sB))  * inv64 + bs.x;
                float v3 = accP[i][j][3] + __half2float(__high2half(sB)) * inv64 + bs.y;
                if (mode == 0) {
                    if (r1 < NN)     *(float2*)(XpOut + (size_t)r1 * 2048 + c0) = make_float2(v0, v1);
                    if (r1 + 8 < NN) *(float2*)(XpOut + (size_t)(r1 + 8) * 2048 + c0) = make_float2(v2, v3);
                } else {  // mode 2: split write
                    if (r1 < NN) {
                        __half h0 = __float2half_rn(v0), h1 = __float2half_rn(v1);
                        __half l0 = __float2half_rn((v0 - __half2float(h0)) * 64.f);
                        __half l1 = __float2half_rn((v1 - __half2float(h1)) * 64.f);
                        size_t o = (size_t)r1 * hstride + hoff + c0;
                        *(__half2*)(hout + o)       = __halves2half2(h0, h1);
                        *(__half2*)(hout + o + 512) = __halves2half2(l0, l1);
                    }
                    if (r1 + 8 < NN) {
                        __half h0 = __float2half_rn(v2), h1 = __float2half_rn(v3);
                        __half l0 = __float2half_rn((v2 - __half2float(h0)) * 64.f);
                        __half l1 = __float2half_rn((v3 - __half2float(h1)) * 64.f);
                        size_t o = (size_t)(r1 + 8) * hstride + hoff + c0;
                        *(__half2*)(hout + o)       = __halves2half2(h0, h1);
                        *(__half2*)(hout + o + 512) = __halves2half2(l0, l1);
                    }
                }
            }
    } else {
        #pragma unroll
        for (int i = 0; i < 2; i++)
            #pragma unroll
            for (int j = 0; j < 4; j++) {
                const __half2 sA = *(const __half2*)&accS[i][j][0];
                const __half2 sB = *(const __half2*)&accS[i][j][1];
                float v0 = accP[i][j][0] + __half2float(__low2half(sA))  * inv64;
                float v1 = accP[i][j][1] + __half2float(__high2half(sA)) * inv64;
                float v2 = accP[i][j][2] + __half2float(__low2half(sB))  * inv64;
                float v3 = accP[i][j][3] + __half2float(__high2half(sB)) * inv64;
                const float p0 = __shfl_xor_sync(0xffffffffu, v0, 1);
                const float p1 = __shfl_xor_sync(0xffffffffu, v1, 1);
                const float p2 = __shfl_xor_sync(0xffffffffu, v2, 1);
                const float p3 = __shfl_xor_sync(0xffffffffu, v3, 1);
                const int q = lane & 1;
                const int rowU = m0 + wm * 32 + i * 16 + (lane >> 2) + (q << 3);
                const int hc = ((n0 + wn * 32 + j * 8) >> 2) + ((lane & 3) >> 1);
                if (rowU < NN) {
                    float gi, gf, gg, go;
                    if (!q) { gi = v0; gf = v1; gg = p0; go = p1; }
                    else    { gi = p2; gf = p3; gg = v2; go = v3; }
                    const int s = src[rowU * DEG + t];
                    const float4 xv = *(const float4*)(XpIn + (size_t)s * 2048 + 4 * hc);
                    gi += xv.x; gf += xv.y; gg += xv.z; go += xv.w;
                    const size_t ci = (size_t)rowU * FF + hc;
                    const float cn = sig_(gf) * cbuf[ci] + sig_(gi) * tanh_(gg);
                    cbuf[ci] = cn;
                    const float hv = sig_(go) * tanh_(cn);
                    if (h32out) h32out[ci] = hv;
                    if (hout) {
                        const __half hh = __float2half_rn(hv);
                        hout[(size_t)rowU * hstride + hoff + hc] = hh;
                        hout[(size_t)rowU * hstride + hoff + 512 + hc] =
                            __float2half_rn((hv - __half2float(hh)) * 64.f);
                    }
                }
            }
    }
}

// ---------------------------------------------------------------------------
// conv_w: W fp32 [2048,512] (rows gate*512+hc) -> split [2048,1024] interleaved
// ---------------------------------------------------------------------------
__global__ void __launch_bounds__(256) conv_w_kernel(
    const float* __restrict__ W, const float* __restrict__ b1, const float* __restrict__ b2,
    __half* __restrict__ W2, float* __restrict__ bsum)
{
    const int idx = blockIdx.x * 256 + threadIdx.x;
    if (idx >= 2048 * 512) return;
    const int jp = idx >> 9, k = idx & 511;
    const int orig = (jp & 3) * 512 + (jp >> 2);
    const float w = W[(size_t)orig * 512 + k];
    const __half hi = __float2half_rn(w);
    W2[(size_t)jp * 1024 + k] = hi;
    W2[(size_t)jp * 1024 + 512 + k] = __float2half_rn((w - __half2float(hi)) * 64.f);
    if (k == 0 && bsum) bsum[jp] = b1[orig] + b2[orig];
}

// conv_w_sage: WbS[512,2048] = [Wself^T hi | Wself^T lo64 | Wneigh^T hi | Wneigh^T lo64]
__global__ void __launch_bounds__(256) conv_w_sage_kernel(
    const float* __restrict__ Ws, const float* __restrict__ Wn,
    __half* __restrict__ W2)
{
    const int idx = blockIdx.x * 256 + threadIdx.x;
    if (idx >= 512 * 512) return;
    const int j = idx >> 9, k = idx & 511;
    const float ws = Ws[(size_t)k * 512 + j];
    const float wn = Wn[(size_t)k * 512 + j];
    const __half hs = __float2half_rn(ws), hn = __float2half_rn(wn);
    const size_t base = (size_t)j * 2048;
    W2[base + k]        = hs;
    W2[base + 512 + k]  = __float2half_rn((ws - __half2float(hs)) * 64.f);
    W2[base + 1024 + k] = hn;
    W2[base + 1536 + k] = __float2half_rn((wn - __half2float(hn)) * 64.f);
}

// conv_a: x fp32 [NN,512] -> split into sageA first half (stride 2048)
__global__ void __launch_bounds__(256) conv_a_kernel(
    const float* __restrict__ X, __half* __restrict__ A2)
{
    const int idx = blockIdx.x * 256 + threadIdx.x;
    if (idx >= NN * 512) return;
    const int n = idx >> 9, k = idx & 511;
    const float v = X[idx];
    const __half hi = __float2half_rn(v);
    A2[(size_t)n * 2048 + k] = hi;
    A2[(size_t)n * 2048 + 512 + k] = __float2half_rn((v - __half2float(hi)) * 64.f);
}

// first LSTM step (t=0): gates = Xp[src[:,0]] (h0=c0=0); write c + h split
__global__ void __launch_bounds__(256) lstm_first_kernel(
    const float* __restrict__ Xp, const int* __restrict__ src,
    float* __restrict__ c, __half* __restrict__ hout)
{
    const int idx = blockIdx.x * 256 + threadIdx.x;
    if (idx >= NN * 512) return;
    const int n = idx >> 9, hc = idx & 511;
    const int s = src[n * DEG];
    const float4 xv = *(const float4*)(Xp + (size_t)s * 2048 + 4 * hc);
    const float cn = sig_(xv.x) * tanh_(xv.z);
    c[idx] = cn;
    const float hv = sig_(xv.w) * tanh_(cn);
    const __half hh = __float2half_rn(hv);
    hout[(size_t)n * 1024 + hc] = hh;
    hout[(size_t)n * 1024 + 512 + hc] = __float2half_rn((hv - __half2float(hh)) * 64.f);
}

// ---------------------------------------------------------------------------
extern "C" void kernel_launch(void* const* d_in, const int* in_sizes, int n_in,
                              void* d_out, int out_size)
{
    const float* x      = (const float*)d_in[0];
    const int*   src    = (const int*)  d_in[1];
    const float* Wih1   = (const float*)d_in[2];
    const float* Whh1   = (const float*)d_in[3];
    const float* bih1   = (const float*)d_in[4];
    const float* bhh1   = (const float*)d_in[5];
    const float* Wself  = (const float*)d_in[6];
    const float* Wneigh = (const float*)d_in[7];
    const float* b      = (const float*)d_in[8];
    const float* Wih2   = (const float*)d_in[9];
    const float* Whh2   = (const float*)d_in[10];
    const float* bih2   = (const float*)d_in[11];
    const float* bhh2   = (const float*)d_in[12];
    float* out = (float*)d_out;

    float *Xp, *bsum, *c;
    __half *sageA, *hA, *hB, *Wb, *WbS;
    cudaGetSymbolAddress((void**)&Xp,    g_Xp);
    cudaGetSymbolAddress((void**)&sageA, g_sageA);
    cudaGetSymbolAddress((void**)&hA,    g_hA);
    cudaGetSymbolAddress((void**)&hB,    g_hB);
    cudaGetSymbolAddress((void**)&Wb,    g_Wb);
    cudaGetSymbolAddress((void**)&WbS,   g_WbS);
    cudaGetSymbolAddress((void**)&bsum,  g_bsum);
    cudaGetSymbolAddress((void**)&c,     g_c);

    cudaFuncSetAttribute(gemm_f16_kernel,
                         cudaFuncAttributeMaxDynamicSharedMemorySize, SMEMB);

    const dim3 gMain((NN + 127) / 128, 16);   // 2048 output cols
    const dim3 gSage((NN + 127) / 128, 4);    // 512 output cols
    const int  gElem  = (NN * 512) / 256;
    const int  gConvW = (2048 * 512) / 256;
    const int  gConvS = (512 * 512) / 256;

    // ================= Stage 1 =================
    conv_w_kernel<<<gConvW, 256>>>(Wih1, bih1, bhh1, Wb, bsum);
    conv_a_kernel<<<gElem, 256>>>(x, sageA);
    gemm_f16_kernel<<<gMain, 512, SMEMB>>>(sageA, 2048, Wb, 1, 0,
        bsum, Xp, nullptr, nullptr, 0, nullptr, nullptr, 0, 0, nullptr);
    conv_w_kernel<<<gConvW, 256>>>(Whh1, nullptr, nullptr, Wb, nullptr);
    lstm_first_kernel<<<gElem, 256>>>(Xp, src, c, hB);          // h(0) -> hB
    for (int t = 1; t <= 30; t++) {
        __half* hin  = (t & 1) ? hB : hA;
        __half* hout = (t & 1) ? hA : hB;
        gemm_f16_kernel<<<gMain, 512, SMEMB>>>(hin, 1024, Wb, 1, 1,
            nullptr, nullptr, Xp, src, t, c, hout, 1024, 0, nullptr);
    }
    // t=31: h_neigh split -> sageA second half
    gemm_f16_kernel<<<gMain, 512, SMEMB>>>(hB, 1024, Wb, 1, 1,
        nullptr, nullptr, Xp, src, 31, c, sageA, 2048, 1024, nullptr);

    // ---- SAGE linear (split output -> hA) ----
    conv_w_sage_kernel<<<gConvS, 256>>>(Wself, Wneigh, WbS);
    gemm_f16_kernel<<<gSage, 512, SMEMB>>>(sageA, 2048, WbS, 2, 2,
        b, nullptr, nullptr, nullptr, 0, nullptr, hA, 1024, 0, nullptr);

    // ================= Stage 2 =================
    conv_w_kernel<<<gConvW, 256>>>(Wih2, bih2, bhh2, Wb, bsum);
    gemm_f16_kernel<<<gMain, 512, SMEMB>>>(hA, 1024, Wb, 1, 0,
        bsum, Xp, nullptr, nullptr, 0, nullptr, nullptr, 0, 0, nullptr);
    conv_w_kernel<<<gConvW, 256>>>(Whh2, nullptr, nullptr, Wb, nullptr);
    lstm_first_kernel<<<gElem, 256>>>(Xp, src, c, hB);
    for (int t = 1; t <= 30; t++) {
        __half* hin  = (t & 1) ? hB : hA;
        __half* hout = (t & 1) ? hA : hB;
        gemm_f16_kernel<<<gMain, 512, SMEMB>>>(hin, 1024, Wb, 1, 1,
            nullptr, nullptr, Xp, src, t, c, hout, 1024, 0, nullptr);
    }
    gemm_f16_kernel<<<gMain, 512, SMEMB>>>(hB, 1024, Wb, 1, 1,
        nullptr, nullptr, Xp, src, 31, c, nullptr, 0, 0, out);
}

// round 6
// speedup vs baseline: 2.0020x; 1.1165x over previous
#include <cuda_runtime.h>
#include <cuda_fp16.h>
#include <cstdint>

#define NN   10000
#define DEG  32
#define FF   512

// ---------------- scratch (static device globals; no allocation) ----------
static __device__ float  g_Xp   [(size_t)NN * 2048];   // gate pre-activations (col = 4*hc+gate)
static __device__ __half g_sageA[(size_t)NN * 1024];   // [x_h | hn_h]  (sage GEMM A, lda=1024)
static __device__ __half g_hA   [(size_t)NN * 512];    // h fp16 ping
static __device__ __half g_hB   [(size_t)NN * 512];    // h fp16 pong
static __device__ __half g_hs16 [(size_t)NN * 512];    // sage output fp16
static __device__ __half g_Wb   [(size_t)2048 * 1024]; // W rows jp: [hi(512) | lo*2048(512)]
static __device__ __half g_WbS  [(size_t)512 * 2048];  // sage W rows j: [hi(1024) | lo*2048(1024)]
static __device__ float  g_bsum [2048];
static __device__ float  g_c    [(size_t)NN * FF];

__device__ __forceinline__ float sig_(float x) {
    return __fdividef(1.0f, 1.0f + __expf(-x));
}
__device__ __forceinline__ float tanh_(float x) {
    float e = __expf(-2.0f * fabsf(x));
    float t = __fdividef(1.0f - e, 1.0f + e);
    return copysignf(t, x);
}
__device__ __forceinline__ uint32_t smem_u32(const void* p) {
    uint32_t a;
    asm("{ .reg .u64 t; cvta.to.shared.u64 t, %1; cvt.u32.u64 %0, t; }" : "=r"(a) : "l"(p));
    return a;
}
__device__ __forceinline__ void cpa16(uint32_t saddr, const void* g, int ss) {
    asm volatile("cp.async.cg.shared.global [%0], [%1], 16, %2;"
                 :: "r"(saddr), "l"(g), "r"(ss) : "memory");
}
__device__ __forceinline__ void ldsm4(uint32_t* r, uint32_t addr) {
    asm volatile("ldmatrix.sync.aligned.m8n8.x4.shared.b16 {%0,%1,%2,%3}, [%4];"
                 : "=r"(r[0]), "=r"(r[1]), "=r"(r[2]), "=r"(r[3]) : "r"(addr));
}
__device__ __forceinline__ void mma16816(float* d, const uint32_t* a, const uint32_t* b) {
    asm volatile("mma.sync.aligned.m16n8k16.row.col.f32.f16.f16.f32 "
                 "{%0,%1,%2,%3}, {%4,%5,%6,%7}, {%8,%9}, {%0,%1,%2,%3};"
                 : "+f"(d[0]), "+f"(d[1]), "+f"(d[2]), "+f"(d[3])
                 : "r"(a[0]), "r"(a[1]), "r"(a[2]), "r"(a[3]), "r"(b[0]), "r"(b[1]));
}
__device__ __forceinline__ void mma16816h(uint32_t* d, const uint32_t* a, const uint32_t* b) {
    asm volatile("mma.sync.aligned.m16n8k16.row.col.f16.f16.f16.f16 "
                 "{%0,%1}, {%2,%3,%4,%5}, {%6,%7}, {%0,%1};"
                 : "+r"(d[0]), "+r"(d[1])
                 : "r"(a[0]), "r"(a[1]), "r"(a[2]), "r"(a[3]), "r"(b[0]), "r"(b[1]));
}

// geometry: block 128x128, 256 threads (8 warps: wm 0..1 x wn 0..3), warp 64x32
// smem per stage: A 128x32 + Bhi 128x32 + Blo 128x32, padded stride 40 halfs
#define PAD     40
#define TILE_B  10240              // 128*40*2
#define STAGE_B 30720              // A + Bhi + Blo
#define NSTAGE  3
#define SMEMB   (NSTAGE * STAGE_B) // 92,160

// ---------------------------------------------------------------------------
// GEMM: C[m, n] = A[m,:K] . (Bhi[n,:K] + Blo[n,:K]/2048)
//   B2 row n (ldb = 2K): [hi(0..K) | lo*2048(K..2K)]
// mode 0: Xp[r*2048 + c] = C + bias[c]            (fp32)
// mode 1: LSTM gate epilogue (Xp gather, c update, h fp16 / fp32 out)
// mode 2: hout fp16 = C + bias[c]                  (hstride/hoff)
// ---------------------------------------------------------------------------
__global__ void __launch_bounds__(256, 1) gemm_f16_kernel(
    const __half* __restrict__ A, int lda,
    const __half* __restrict__ B2, int K, int mode,
    const float* __restrict__ bias, float* __restrict__ XpOut,
    const float* __restrict__ XpIn, const int* __restrict__ src, int t,
    float* __restrict__ cbuf,
    __half* __restrict__ hout, int hstride, int hoff,
    float* __restrict__ h32out)
{
    extern __shared__ __align__(16) char smem[];
    const uint32_t sbase = smem_u32(smem);
    const int tid  = threadIdx.x;
    const int warp = tid >> 5, lane = tid & 31;
    const int wn = warp & 3, wm = warp >> 2;
    const int m0 = blockIdx.x * 128, n0 = blockIdx.y * 128;
    const int ldb = K << 1;
    const int nch = K >> 5;

    float    accP[4][4][4];
    uint32_t accS[4][4][2];
    #pragma unroll
    for (int mi = 0; mi < 4; mi++)
        #pragma unroll
        for (int nj = 0; nj < 4; nj++) {
            #pragma unroll
            for (int r = 0; r < 4; r++) accP[mi][nj][r] = 0.f;
            accS[mi][nj][0] = 0u; accS[mi][nj][1] = 0u;
        }

    // load mapping (256 threads):
    //   A tile 128x32 halfs: 2 x 16B per thread (rows tid>>2 and 64+(tid>>2))
    //   B tiles (hi+lo) 128x32 each: 2 x 16B per tile via rows tid>>2, 64+(tid>>2)
    const int r0 = tid >> 2, seg = tid & 3;
    const int r1r = r0 + 64;
    const int asz0 = (m0 + r0  < NN) ? 16 : 0;
    const int asz1 = (m0 + r1r < NN) ? 16 : 0;
    const size_t aG0 = (size_t)((m0 + r0  < NN) ? (m0 + r0)  : 0) * lda + seg * 8;
    const size_t aG1 = (size_t)((m0 + r1r < NN) ? (m0 + r1r) : 0) * lda + seg * 8;
    const uint32_t aSm0 = (uint32_t)(r0  * PAD + seg * 8) * 2;
    const uint32_t aSm1 = (uint32_t)(r1r * PAD + seg * 8) * 2;
    const size_t bG0 = (size_t)(n0 + r0)  * ldb + seg * 8;
    const size_t bG1 = (size_t)(n0 + r1r) * ldb + seg * 8;
    const uint32_t bSm0 = aSm0, bSm1 = aSm1;

    // ldmatrix lane offsets
    const uint32_t aL = (uint32_t)((lane & 15) * PAD + (lane >> 4) * 8) * 2;
    const uint32_t bL = (uint32_t)(((lane & 7) + ((lane >> 4) << 3)) * PAD
                                   + ((lane >> 3) & 1) * 8) * 2;
    const uint32_t aWm = (uint32_t)(wm * 64 * PAD) * 2;
    const uint32_t bWn = (uint32_t)(wn * 32 * PAD) * 2;

    auto issue = [&](int ch, int buf) {
        const int kc = ch << 5;
        const uint32_t s0 = sbase + buf * STAGE_B;
        cpa16(s0 + aSm0, A + aG0 + kc, asz0);
        cpa16(s0 + aSm1, A + aG1 + kc, asz1);
        cpa16(s0 + TILE_B     + bSm0, B2 + bG0 + kc,     16);
        cpa16(s0 + TILE_B     + bSm1, B2 + bG1 + kc,     16);
        cpa16(s0 + 2 * TILE_B + bSm0, B2 + bG0 + K + kc, 16);
        cpa16(s0 + 2 * TILE_B + bSm1, B2 + bG1 + K + kc, 16);
        asm volatile("cp.async.commit_group;" ::: "memory");
    };

    issue(0, 0);
    issue(1, 1);
    int buf = 0;
    #pragma unroll 1
    for (int ch = 0; ch < nch; ch++) {
        if (ch + 1 < nch)
            asm volatile("cp.async.wait_group 1;" ::: "memory");
        else
            asm volatile("cp.async.wait_group 0;" ::: "memory");
        __syncthreads();
        if (ch + 2 < nch) {
            int nb = buf + 2; if (nb >= NSTAGE) nb -= NSTAGE;
            issue(ch + 2, nb);
        }
        const uint32_t s0 = sbase + buf * STAGE_B;
        #pragma unroll
        for (int ks = 0; ks < 2; ks++) {
            uint32_t aH[4][4], bH[2][4], bLo[2][4];
            #pragma unroll
            for (int mi = 0; mi < 4; mi++)
                ldsm4(aH[mi], s0 + aWm + aL + (uint32_t)(mi * 16 * PAD + ks * 16) * 2);
            #pragma unroll
            for (int njp = 0; njp < 2; njp++) {
                ldsm4(bH[njp],  s0 + TILE_B     + bWn + bL + (uint32_t)(njp * 16 * PAD + ks * 16) * 2);
                ldsm4(bLo[njp], s0 + 2 * TILE_B + bWn + bL + (uint32_t)(njp * 16 * PAD + ks * 16) * 2);
            }
            #pragma unroll
            for (int mi = 0; mi < 4; mi++)
                #pragma unroll
                for (int nj = 0; nj < 4; nj++) {
                    mma16816(accP[mi][nj], aH[mi], &bH[nj >> 1][(nj & 1) * 2]);
                    mma16816h(accS[mi][nj], aH[mi], &bLo[nj >> 1][(nj & 1) * 2]);
                }
        }
        buf++; if (buf >= NSTAGE) buf -= NSTAGE;
    }

    const float invS = 1.0f / 2048.0f;

    if (mode != 1) {
        #pragma unroll
        for (int mi = 0; mi < 4; mi++)
            #pragma unroll
            for (int nj = 0; nj < 4; nj++) {
                const int c0 = n0 + wn * 32 + nj * 8 + (lane & 3) * 2;
                const int rr = m0 + wm * 64 + mi * 16 + (lane >> 2);
                const __half2 sA = *(const __half2*)&accS[mi][nj][0];
                const __half2 sB = *(const __half2*)&accS[mi][nj][1];
                const float2 bs = make_float2(bias[c0], bias[c0 + 1]);
                float v0 = accP[mi][nj][0] + __half2float(__low2half(sA))  * invS + bs.x;
                float v1 = accP[mi][nj][1] + __half2float(__high2half(sA)) * invS + bs.y;
                float v2 = accP[mi][nj][2] + __half2float(__low2half(sB))  * invS + bs.x;
                float v3 = accP[mi][nj][3] + __half2float(__high2half(sB)) * invS + bs.y;
                if (mode == 0) {
                    if (rr < NN)     *(float2*)(XpOut + (size_t)rr * 2048 + c0) = make_float2(v0, v1);
                    if (rr + 8 < NN) *(float2*)(XpOut + (size_t)(rr + 8) * 2048 + c0) = make_float2(v2, v3);
                } else {  // mode 2: fp16 write
                    if (rr < NN)
                        *(__half2*)(hout + (size_t)rr * hstride + hoff + c0) =
                            __halves2half2(__float2half_rn(v0), __float2half_rn(v1));
                    if (rr + 8 < NN)
                        *(__half2*)(hout + (size_t)(rr + 8) * hstride + hoff + c0) =
                            __halves2half2(__float2half_rn(v2), __float2half_rn(v3));
                }
            }
    } else {
        #pragma unroll
        for (int mi = 0; mi < 4; mi++)
            #pragma unroll
            for (int nj = 0; nj < 4; nj++) {
                const __half2 sA = *(const __half2*)&accS[mi][nj][0];
                const __half2 sB = *(const __half2*)&accS[mi][nj][1];
                float v0 = accP[mi][nj][0] + __half2float(__low2half(sA))  * invS;
                float v1 = accP[mi][nj][1] + __half2float(__high2half(sA)) * invS;
                float v2 = accP[mi][nj][2] + __half2float(__low2half(sB))  * invS;
                float v3 = accP[mi][nj][3] + __half2float(__high2half(sB)) * invS;
                const float p0 = __shfl_xor_sync(0xffffffffu, v0, 1);
                const float p1 = __shfl_xor_sync(0xffffffffu, v1, 1);
                const float p2 = __shfl_xor_sync(0xffffffffu, v2, 1);
                const float p3 = __shfl_xor_sync(0xffffffffu, v3, 1);
                const int q = lane & 1;
                const int rowU = m0 + wm * 64 + mi * 16 + (lane >> 2) + (q << 3);
                const int hc = ((n0 + wn * 32 + nj * 8) >> 2) + ((lane & 3) >> 1);
                if (rowU < NN) {
                    float gi, gf, gg, go;
                    if (!q) { gi = v0; gf = v1; gg = p0; go = p1; }
                    else    { gi = p2; gf = p3; gg = v2; go = v3; }
                    const int s = src[rowU * DEG + t];
                    const float4 xv = *(const float4*)(XpIn + (size_t)s * 2048 + 4 * hc);
                    gi += xv.x; gf += xv.y; gg += xv.z; go += xv.w;
                    const size_t ci = (size_t)rowU * FF + hc;
                    const float cn = sig_(gf) * cbuf[ci] + sig_(gi) * tanh_(gg);
                    cbuf[ci] = cn;
                    const float hv = sig_(go) * tanh_(cn);
                    if (h32out) h32out[ci] = hv;
                    if (hout) hout[(size_t)rowU * hstride + hoff + hc] = __float2half_rn(hv);
                }
            }
    }
}

// ---------------------------------------------------------------------------
// conv_w: W fp32 [2048,512] (rows gate*512+hc) -> [2048][1024]: [hi | lo*2048]
// row jp = 4*hc + gate; bsum[jp] = b1 + b2
// ---------------------------------------------------------------------------
__global__ void __launch_bounds__(256) conv_w_kernel(
    const float* __restrict__ W, const float* __restrict__ b1, const float* __restrict__ b2,
    __half* __restrict__ W2, float* __restrict__ bsum)
{
    const int idx = blockIdx.x * 256 + threadIdx.x;
    if (idx >= 2048 * 512) return;
    const int jp = idx >> 9, k = idx & 511;
    const int orig = (jp & 3) * 512 + (jp >> 2);
    const float w = W[(size_t)orig * 512 + k];
    const __half hi = __float2half_rn(w);
    W2[(size_t)jp * 1024 + k] = hi;
    W2[(size_t)jp * 1024 + 512 + k] = __float2half_rn((w - __half2float(hi)) * 2048.f);
    if (k == 0 && bsum) bsum[jp] = b1[orig] + b2[orig];
}

// conv_w_sage: WbS[512][2048]: row j: [hi(Wcat[:,j]) (1024) | lo*2048 (1024)]
// Wcat rows 0..511 = Wself, 512..1023 = Wneigh
__global__ void __launch_bounds__(256) conv_w_sage_kernel(
    const float* __restrict__ Ws, const float* __restrict__ Wn,
    __half* __restrict__ W2)
{
    const int idx = blockIdx.x * 256 + threadIdx.x;
    if (idx >= 512 * 1024) return;
    const int j = idx >> 10, k = idx & 1023;
    const float w = (k < 512) ? Ws[(size_t)k * 512 + j] : Wn[(size_t)(k - 512) * 512 + j];
    const __half hi = __float2half_rn(w);
    W2[(size_t)j * 2048 + k] = hi;
    W2[(size_t)j * 2048 + 1024 + k] = __float2half_rn((w - __half2float(hi)) * 2048.f);
}

// conv_a: x fp32 -> fp16 into sageA cols 0..511 (stride 1024)
__global__ void __launch_bounds__(256) conv_a_kernel(
    const float* __restrict__ X, __half* __restrict__ A2)
{
    const int idx = blockIdx.x * 256 + threadIdx.x;
    if (idx >= NN * 512) return;
    const int n = idx >> 9, k = idx & 511;
    A2[(size_t)n * 1024 + k] = __float2half_rn(X[idx]);
}

// first LSTM step (t=0): gates = Xp[src[:,0]]; write c + h fp16
__global__ void __launch_bounds__(256) lstm_first_kernel(
    const float* __restrict__ Xp, const int* __restrict__ src,
    float* __restrict__ c, __half* __restrict__ hout)
{
    const int idx = blockIdx.x * 256 + threadIdx.x;
    if (idx >= NN * 512) return;
    const int n = idx >> 9, hc = idx & 511;
    const int s = src[n * DEG];
    const float4 xv = *(const float4*)(Xp + (size_t)s * 2048 + 4 * hc);
    const float cn = sig_(xv.x) * tanh_(xv.z);
    c[idx] = cn;
    hout[idx] = __float2half_rn(sig_(xv.w) * tanh_(cn));
}

// ---------------------------------------------------------------------------
extern "C" void kernel_launch(void* const* d_in, const int* in_sizes, int n_in,
                              void* d_out, int out_size)
{
    const float* x      = (const float*)d_in[0];
    const int*   src    = (const int*)  d_in[1];
    const float* Wih1   = (const float*)d_in[2];
    const float* Whh1   = (const float*)d_in[3];
    const float* bih1   = (const float*)d_in[4];
    const float* bhh1   = (const float*)d_in[5];
    const float* Wself  = (const float*)d_in[6];
    const float* Wneigh = (const float*)d_in[7];
    const float* b      = (const float*)d_in[8];
    const float* Wih2   = (const float*)d_in[9];
    const float* Whh2   = (const float*)d_in[10];
    const float* bih2   = (const float*)d_in[11];
    const float* bhh2   = (const float*)d_in[12];
    float* out = (float*)d_out;

    float *Xp, *bsum, *c;
    __half *sageA, *hA, *hB, *hs16, *Wb, *WbS;
    cudaGetSymbolAddress((void**)&Xp,    g_Xp);
    cudaGetSymbolAddress((void**)&sageA, g_sageA);
    cudaGetSymbolAddress((void**)&hA,    g_hA);
    cudaGetSymbolAddress((void**)&hB,    g_hB);
    cudaGetSymbolAddress((void**)&hs16,  g_hs16);
    cudaGetSymbolAddress((void**)&Wb,    g_Wb);
    cudaGetSymbolAddress((void**)&WbS,   g_WbS);
    cudaGetSymbolAddress((void**)&bsum,  g_bsum);
    cudaGetSymbolAddress((void**)&c,     g_c);

    cudaFuncSetAttribute(gemm_f16_kernel,
                         cudaFuncAttributeMaxDynamicSharedMemorySize, SMEMB);

    const dim3 gMain((NN + 127) / 128, 16);   // 2048 output cols
    const dim3 gSage((NN + 127) / 128, 4);    // 512 output cols
    const int  gElem  = (NN * 512) / 256;
    const int  gConvW = (2048 * 512) / 256;
    const int  gConvS = (512 * 1024) / 256;

    // ================= Stage 1 =================
    conv_w_kernel<<<gConvW, 256>>>(Wih1, bih1, bhh1, Wb, bsum);
    conv_a_kernel<<<gElem, 256>>>(x, sageA);
    gemm_f16_kernel<<<gMain, 256, SMEMB>>>(sageA, 1024, Wb, 512, 0,
        bsum, Xp, nullptr, nullptr, 0, nullptr, nullptr, 0, 0, nullptr);
    conv_w_kernel<<<gConvW, 256>>>(Whh1, nullptr, nullptr, Wb, nullptr);
    lstm_first_kernel<<<gElem, 256>>>(Xp, src, c, hB);          // h(0) -> hB
    for (int t = 1; t <= 30; t++) {
        __half* hin  = (t & 1) ? hB : hA;
        __half* hout = (t & 1) ? hA : hB;
        gemm_f16_kernel<<<gMain, 256, SMEMB>>>(hin, 512, Wb, 512, 1,
            nullptr, nullptr, Xp, src, t, c, hout, 512, 0, nullptr);
    }
    // t=31: h_neigh fp16 -> sageA cols 512..1023
    gemm_f16_kernel<<<gMain, 256, SMEMB>>>(hB, 512, Wb, 512, 1,
        nullptr, nullptr, Xp, src, 31, c, sageA, 1024, 512, nullptr);

    // ---- SAGE linear: hs16 = sageA . WbS^T + b ----
    conv_w_sage_kernel<<<gConvS, 256>>>(Wself, Wneigh, WbS);
    gemm_f16_kernel<<<gSage, 256, SMEMB>>>(sageA, 1024, WbS, 1024, 2,
        b, nullptr, nullptr, nullptr, 0, nullptr, hs16, 512, 0, nullptr);

    // ================= Stage 2 =================
    conv_w_kernel<<<gConvW, 256>>>(Wih2, bih2, bhh2, Wb, bsum);
    gemm_f16_kernel<<<gMain, 256, SMEMB>>>(hs16, 512, Wb, 512, 0,
        bsum, Xp, nullptr, nullptr, 0, nullptr, nullptr, 0, 0, nullptr);
    conv_w_kernel<<<gConvW, 256>>>(Whh2, nullptr, nullptr, Wb, nullptr);
    lstm_first_kernel<<<gElem, 256>>>(Xp, src, c, hB);
    for (int t = 1; t <= 30; t++) {
        __half* hin  = (t & 1) ? hB : hA;
        __half* hout = (t & 1) ? hA : hB;
        gemm_f16_kernel<<<gMain, 256, SMEMB>>>(hin, 512, Wb, 512, 1,
            nullptr, nullptr, Xp, src, t, c, hout, 512, 0, nullptr);
    }
    gemm_f16_kernel<<<gMain, 256, SMEMB>>>(hB, 512, Wb, 512, 1,
        nullptr, nullptr, Xp, src, 31, c, nullptr, 0, 0, out);
}